// round 4
// baseline (speedup 1.0000x reference)
#include <cuda_runtime.h>
#include <cstdint>

#define B_  32
#define S_  2048
#define C_  1024
#define G_  16
#define K_  256

__device__ float         g_norms[B_ * G_ * S_];   // (B*g, S) row-major
__device__ unsigned char g_mask [B_ * G_ * S_];

// ---------------------------------------------------------------------------
// K1: sum-of-squares per (b,s,group). 16 bs-rows per block, 256 threads,
// front-batched streaming loads (MLP_p1 = 16).
// ---------------------------------------------------------------------------
__global__ __launch_bounds__(256) void k_norms(const float* __restrict__ x) {
    const int base_bs = blockIdx.x << 4;
    const int t = threadIdx.x;
    float4 v[16];
    #pragma unroll
    for (int r = 0; r < 16; r++)
        v[r] = __ldcs(reinterpret_cast<const float4*>(
                          x + (size_t)(base_bs + r) * C_) + t);
    const int b  = base_bs >> 11;           // 16 rows never straddle a batch
    const int s0 = base_bs & (S_ - 1);
    const int g  = t >> 4;
    #pragma unroll
    for (int r = 0; r < 16; r++) {
        float ss = v[r].x * v[r].x + v[r].y * v[r].y
                 + v[r].z * v[r].z + v[r].w * v[r].w;
        #pragma unroll
        for (int off = 8; off > 0; off >>= 1)
            ss += __shfl_down_sync(0xffffffffu, ss, off, 16);
        if ((t & 15) == 0)
            g_norms[((b << 4) + g) * S_ + (s0 + r)] = ss;
    }
}

// ---------------------------------------------------------------------------
// K2: exact Kth-largest per row via 4-pass radix select on the monotone uint
// encoding (values >= 0). Exact-K mask with tie fill. 512 blocks x 512 thr.
// ---------------------------------------------------------------------------
__global__ __launch_bounds__(512) void k_select() {
    __shared__ unsigned int vals[S_];
    __shared__ int hist[256];
    __shared__ int sh_k;
    __shared__ unsigned int sh_prefix;
    __shared__ int n_gt, eq_cnt;

    const int row = blockIdx.x;
    const int tid = threadIdx.x;
    const float* nr = g_norms + (size_t)row * S_;

    #pragma unroll
    for (int i = tid; i < S_; i += 512)
        vals[i] = __float_as_uint(nr[i]);
    if (tid == 0) { sh_k = K_; sh_prefix = 0u; n_gt = 0; eq_cnt = 0; }
    if (tid < 256) hist[tid] = 0;
    __syncthreads();

    int k = K_;
    unsigned int prefix = 0u;
    #pragma unroll
    for (int shift = 24; shift >= 0; shift -= 8) {
        if (shift == 24) {
            #pragma unroll
            for (int i = tid; i < S_; i += 512)
                atomicAdd(&hist[vals[i] >> 24], 1);
        } else {
            const unsigned int pmask = 0xFFFFFFFFu << (shift + 8);
            #pragma unroll
            for (int i = tid; i < S_; i += 512) {
                const unsigned int u = vals[i];
                if ((u & pmask) == prefix)
                    atomicAdd(&hist[(u >> shift) & 255], 1);
            }
        }
        __syncthreads();

        if (tid < 32) {
            const int binbase = 255 - tid * 8;  // lane 0 owns top bins
            int c = 0;
            #pragma unroll
            for (int j = 0; j < 8; j++) c += hist[binbase - j];
            int inc = c;
            #pragma unroll
            for (int off = 1; off < 32; off <<= 1) {
                const int nth = __shfl_up_sync(0xffffffffu, inc, off);
                if (tid >= off) inc += nth;
            }
            const int pre = inc - c;
            const bool hit = (pre < k) && (pre + c >= k);
            const unsigned int bal = __ballot_sync(0xffffffffu, hit);
            if (tid == (__ffs(bal) - 1)) {
                int cum = pre;
                #pragma unroll
                for (int j = 0; j < 8; j++) {
                    const int h = hist[binbase - j];
                    if (cum + h >= k) {
                        sh_k = k - cum;
                        sh_prefix = prefix |
                            ((unsigned int)(binbase - j) << shift);
                        break;
                    }
                    cum += h;
                }
            }
        }
        __syncthreads();
        k = sh_k;
        prefix = sh_prefix;
        if (tid < 256) hist[tid] = 0;   // safe: scan already consumed hist
        __syncthreads();
    }

    const float thr = __uint_as_float(prefix);  // exact Kth largest

    int loc = 0;
    #pragma unroll
    for (int i = tid; i < S_; i += 512)
        loc += (__uint_as_float(vals[i]) > thr) ? 1 : 0;
    #pragma unroll
    for (int off = 16; off > 0; off >>= 1)
        loc += __shfl_down_sync(0xffffffffu, loc, off);
    if ((tid & 31) == 0) atomicAdd(&n_gt, loc);
    __syncthreads();

    const int ngt = n_gt;
    unsigned char* mrow = g_mask + (size_t)row * S_;
    #pragma unroll
    for (int i = tid; i < S_; i += 512) {
        const float v = __uint_as_float(vals[i]);
        unsigned char m = 0;
        if (v > thr) m = 1;
        else if (v == thr) {
            const int p = atomicAdd(&eq_cnt, 1);
            m = (ngt + p < K_) ? 1 : 0;
        }
        mrow[i] = m;
    }
}

// ---------------------------------------------------------------------------
// K3: apply mask. 16 bs-rows per block; one uint4 load fetches all 16 mask
// bytes per thread (same (b,g) row, consecutive s). Front-batched predicated
// streaming loads, streaming stores. MLP_p1 = 16.
// ---------------------------------------------------------------------------
__global__ __launch_bounds__(256) void k_apply(const float* __restrict__ x,
                                               float* __restrict__ out) {
    const int base_bs = blockIdx.x << 4;   // aligned to 16; same b for all
    const int t  = threadIdx.x;
    const int g  = t >> 4;
    const int b  = base_bs >> 11;
    const int s0 = base_bs & (S_ - 1);

    const uint4 mv = *reinterpret_cast<const uint4*>(
        &g_mask[(size_t)((b << 4) + g) * S_ + s0]);
    unsigned int mw[4] = {mv.x, mv.y, mv.z, mv.w};

    float4 v[16];
    #pragma unroll
    for (int r = 0; r < 16; r++) {
        v[r] = make_float4(0.f, 0.f, 0.f, 0.f);
        if ((mw[r >> 2] >> ((r & 3) << 3)) & 0xFFu)
            v[r] = __ldcs(reinterpret_cast<const float4*>(
                              x + (size_t)(base_bs + r) * C_) + t);
    }
    #pragma unroll
    for (int r = 0; r < 16; r++)
        __stcs(reinterpret_cast<float4*>(
                   out + (size_t)(base_bs + r) * C_) + t, v[r]);
}

extern "C" void kernel_launch(void* const* d_in, const int* in_sizes, int n_in,
                              void* d_out, int out_size) {
    const float* x = (const float*)d_in[0];
    float* out = (float*)d_out;
    k_norms <<<(B_ * S_) / 16, 256>>>(x);
    k_select<<<B_ * G_, 512>>>();
    k_apply <<<(B_ * S_) / 16, 256>>>(x, out);
}